// round 1
// baseline (speedup 1.0000x reference)
#include <cuda_runtime.h>
#include <cuda_bf16.h>
#include <math.h>

#define NN_MAX 100000
#define FG 128
#define FIN 512
#define GMAX 512
#define ZD 64
#define HID 64

// ---------------- scratch (device globals: no allocation allowed) ----------------
__device__ float g_xw  [NN_MAX * FG];   // x @ Wg
__device__ float g_agg [NN_MAX * FG];   // neighbor aggregation
__device__ float g_dinv[NN_MAX];        // 1/sqrt(deg)
__device__ float g_psum[GMAX * FG];     // pool sum
__device__ unsigned g_pmax[GMAX * FG];  // pool max (float bits, all vals >= 0)
__device__ float g_cnt [GMAX];          // nodes per graph

// ---------------- init ----------------
__global__ void k_init(int N) {
    int i = blockIdx.x * blockDim.x + threadIdx.x;
    int tot = N * FG;
    if (i < tot) g_agg[i] = 0.f;
    if (i < GMAX * FG) { g_psum[i] = 0.f; g_pmax[i] = 0u; }
    if (i < GMAX) g_cnt[i] = 0.f;
    if (i < N) g_dinv[i] = 1.0f;   // self-loop contributes 1 to degree
}

// ---------------- degree ----------------
__global__ void k_deg(const int* __restrict__ dst, int E) {
    int e = blockIdx.x * blockDim.x + threadIdx.x;
    if (e < E) atomicAdd(&g_dinv[dst[e]], 1.0f);
}

__global__ void k_rsqrt(int N) {
    int i = blockIdx.x * blockDim.x + threadIdx.x;
    if (i < N) g_dinv[i] = rsqrtf(g_dinv[i]);
}

// ---------------- SGEMM: xw = x[N,512] @ Wg[512,128] ----------------
#define BM 128
#define BN 128
#define BK 16
__global__ __launch_bounds__(256, 2)
void k_gemm(const float* __restrict__ X, const float* __restrict__ W, int M) {
    __shared__ float As[BK][BM];
    __shared__ float Bs[BK][BN];
    int tid = threadIdx.x;
    int block_row = blockIdx.x * BM;
    int tx = tid & 15, ty = tid >> 4;
    float acc[8][8];
#pragma unroll
    for (int i = 0; i < 8; i++)
#pragma unroll
        for (int j = 0; j < 8; j++) acc[i][j] = 0.f;

    for (int k0 = 0; k0 < FIN; k0 += BK) {
        // A tile: 128 rows x 16 k (transposed to smem), 512 float4 loads
#pragma unroll
        for (int i = 0; i < 2; i++) {
            int idx = tid + i * 256;
            int row = idx >> 2;
            int k4  = (idx & 3) * 4;
            int grow = block_row + row;
            float4 v = make_float4(0.f, 0.f, 0.f, 0.f);
            if (grow < M) v = *(const float4*)&X[(size_t)grow * FIN + k0 + k4];
            As[k4 + 0][row] = v.x; As[k4 + 1][row] = v.y;
            As[k4 + 2][row] = v.z; As[k4 + 3][row] = v.w;
        }
        // B tile: 16 k x 128 n
#pragma unroll
        for (int i = 0; i < 2; i++) {
            int idx = tid + i * 256;
            int kr = idx >> 5;
            int c4 = (idx & 31) * 4;
            *(float4*)&Bs[kr][c4] = *(const float4*)&W[(k0 + kr) * FG + c4];
        }
        __syncthreads();
#pragma unroll
        for (int kk = 0; kk < BK; kk++) {
            float a[8], b[8];
#pragma unroll
            for (int i = 0; i < 8; i++) a[i] = As[kk][ty * 8 + i];
#pragma unroll
            for (int j = 0; j < 8; j++) b[j] = Bs[kk][tx * 8 + j];
#pragma unroll
            for (int i = 0; i < 8; i++)
#pragma unroll
                for (int j = 0; j < 8; j++) acc[i][j] = fmaf(a[i], b[j], acc[i][j]);
        }
        __syncthreads();
    }
#pragma unroll
    for (int i = 0; i < 8; i++) {
        int grow = block_row + ty * 8 + i;
        if (grow < M) {
#pragma unroll
            for (int j = 0; j < 8; j += 4) {
                float4 v = make_float4(acc[i][j], acc[i][j+1], acc[i][j+2], acc[i][j+3]);
                *(float4*)&g_xw[(size_t)grow * FG + tx * 8 + j] = v;
            }
        }
    }
}

// ---------------- edge scatter: agg[dst] += xw[src] * dinv[src]*dinv[dst] ----------------
__global__ void k_edge(const int* __restrict__ src, const int* __restrict__ dst, int E) {
    int t = blockIdx.x * blockDim.x + threadIdx.x;
    int e = t >> 5, lane = t & 31;
    if (e >= E) return;
    int s = src[e], d = dst[e];
    float w = g_dinv[s] * g_dinv[d];
    float4 v = *(const float4*)&g_xw[s * FG + lane * 4];
    float* p = &g_agg[d * FG + lane * 4];
    asm volatile("red.global.add.v4.f32 [%0], {%1,%2,%3,%4};"
                 :: "l"(p), "f"(v.x * w), "f"(v.y * w), "f"(v.z * w), "f"(v.w * w)
                 : "memory");
}

// ---------------- node finish + pooling ----------------
__global__ void k_node_pool(const int* __restrict__ batch, const float* __restrict__ bg, int N) {
    int t = blockIdx.x * blockDim.x + threadIdx.x;
    int n = t >> 5, lane = t & 31;
    if (n >= N) return;
    float di = g_dinv[n];
    float sl = di * di;               // self-loop norm
    float4 a  = *(const float4*)&g_agg[n * FG + lane * 4];
    float4 xv = *(const float4*)&g_xw[n * FG + lane * 4];
    float4 bv = *(const float4*)&bg[lane * 4];
    float v0 = fmaxf(fmaf(xv.x, sl, a.x) + bv.x, 0.f);
    float v1 = fmaxf(fmaf(xv.y, sl, a.y) + bv.y, 0.f);
    float v2 = fmaxf(fmaf(xv.z, sl, a.z) + bv.z, 0.f);
    float v3 = fmaxf(fmaf(xv.w, sl, a.w) + bv.w, 0.f);
    int b = batch[n];
    float* ps = &g_psum[b * FG + lane * 4];
    asm volatile("red.global.add.v4.f32 [%0], {%1,%2,%3,%4};"
                 :: "l"(ps), "f"(v0), "f"(v1), "f"(v2), "f"(v3) : "memory");
    int* pm = (int*)&g_pmax[b * FG + lane * 4];
    atomicMax(pm + 0, __float_as_int(v0));   // all vals >= 0: int cmp == float cmp
    atomicMax(pm + 1, __float_as_int(v1));
    atomicMax(pm + 2, __float_as_int(v2));
    atomicMax(pm + 3, __float_as_int(v3));
    if (lane == 0) atomicAdd(&g_cnt[b], 1.0f);
}

// ---------------- head: encoder/decoder MLPs, one block per graph ----------------
__device__ __forceinline__ float eluf(float x)      { return x > 0.f ? x : expm1f(x); }
__device__ __forceinline__ float softplusf(float x) { return x > 20.f ? x : log1pf(expf(x)); }

__global__ void k_head(const float* __restrict__ eps,
                       const float* __restrict__ We1, const float* __restrict__ be1,
                       const float* __restrict__ We2, const float* __restrict__ be2,
                       const float* __restrict__ We3, const float* __restrict__ be3,
                       const float* __restrict__ Wd1, const float* __restrict__ bd1,
                       const float* __restrict__ Wd2, const float* __restrict__ bd2,
                       const float* __restrict__ Wd3, const float* __restrict__ bd3,
                       float* __restrict__ out, int G) {
    __shared__ float gx[2 * FG];
    __shared__ float t1[HID], t2[HID], ml[2 * ZD], zz[ZD], dd1[HID], dd2[HID];
    int g = blockIdx.x;
    int tid = threadIdx.x;

    float cnt = fmaxf(g_cnt[g], 1.0f);
    gx[tid]      = g_psum[g * FG + tid] / cnt;          // mean pool
    gx[FG + tid] = __int_as_float(g_pmax[g * FG + tid]); // max pool
    __syncthreads();

    if (tid < HID) {
        float s = be1[tid];
#pragma unroll 8
        for (int i = 0; i < 2 * FG; i++) s = fmaf(gx[i], We1[i * HID + tid], s);
        t1[tid] = eluf(s);
    }
    __syncthreads();
    if (tid < HID) {
        float s = be2[tid];
#pragma unroll 8
        for (int i = 0; i < HID; i++) s = fmaf(t1[i], We2[i * HID + tid], s);
        t2[tid] = tanhf(s);
    }
    __syncthreads();
    {   // ml = t2 @ We3 + be3  (128 outputs)
        float s = be3[tid];
#pragma unroll 8
        for (int i = 0; i < HID; i++) s = fmaf(t2[i], We3[i * 2 * ZD + tid], s);
        ml[tid] = s;
    }
    __syncthreads();
    if (tid < ZD) {
        float mu = ml[tid];
        float sd = 1e-6f + softplusf(ml[ZD + tid]);
        float z = fmaf(eps[g * ZD + tid], sd, mu);
        zz[tid] = z;
        out[g * ZD + tid] = mu;                 // mu block
        out[G * ZD + g * ZD + tid] = sd;        // stddev block
    }
    __syncthreads();
    if (tid < HID) {
        float s = bd1[tid];
#pragma unroll 8
        for (int i = 0; i < ZD; i++) s = fmaf(zz[i], Wd1[i * HID + tid], s);
        dd1[tid] = tanhf(s);
    }
    __syncthreads();
    if (tid < HID) {
        float s = bd2[tid];
#pragma unroll 8
        for (int i = 0; i < HID; i++) s = fmaf(dd1[i], Wd2[i * HID + tid], s);
        dd2[tid] = eluf(s);
    }
    __syncthreads();
    {   // y = sigmoid(dd2 @ Wd3 + bd3), 128 outputs
        float s = bd3[tid];
#pragma unroll 8
        for (int i = 0; i < HID; i++) s = fmaf(dd2[i], Wd3[i * FG + tid], s);
        float y = 1.0f / (1.0f + expf(-s));
        y = fminf(fmaxf(y, 1e-8f), 1.0f - 1e-8f);
        out[2 * G * ZD + g * FG + tid] = y;     // y block
    }
}

// ---------------- launch ----------------
extern "C" void kernel_launch(void* const* d_in, const int* in_sizes, int n_in,
                              void* d_out, int out_size) {
    const float* x     = (const float*)d_in[0];
    const int*   ei    = (const int*)  d_in[1];
    const int*   batch = (const int*)  d_in[2];
    const float* eps   = (const float*)d_in[3];
    const float* Wg    = (const float*)d_in[4];
    const float* bg    = (const float*)d_in[5];
    const float* We1 = (const float*)d_in[6],  *be1 = (const float*)d_in[7];
    const float* We2 = (const float*)d_in[8],  *be2 = (const float*)d_in[9];
    const float* We3 = (const float*)d_in[10], *be3 = (const float*)d_in[11];
    const float* Wd1 = (const float*)d_in[12], *bd1 = (const float*)d_in[13];
    const float* Wd2 = (const float*)d_in[14], *bd2 = (const float*)d_in[15];
    const float* Wd3 = (const float*)d_in[16], *bd3 = (const float*)d_in[17];
    float* out = (float*)d_out;

    int N = in_sizes[0] / FIN;       // 100000
    int E = in_sizes[1] / 2;         // 1600000
    int G = in_sizes[3] / ZD;        // 512
    const int* src = ei;
    const int* dst = ei + E;

    k_init<<<(N * FG + 255) / 256, 256>>>(N);
    k_deg<<<(E + 255) / 256, 256>>>(dst, E);
    k_rsqrt<<<(N + 255) / 256, 256>>>(N);
    k_gemm<<<(N + BM - 1) / BM, 256>>>(x, Wg, N);
    {
        long long t = (long long)E * 32;
        k_edge<<<(int)((t + 255) / 256), 256>>>(src, dst, E);
    }
    {
        long long t = (long long)N * 32;
        k_node_pool<<<(int)((t + 255) / 256), 256>>>(batch, bg, N);
    }
    k_head<<<G, 128>>>(eps, We1, be1, We2, be2, We3, be3,
                       Wd1, bd1, Wd2, bd2, Wd3, bd3, out, G);
}

// round 2
// speedup vs baseline: 1.4131x; 1.4131x over previous
#include <cuda_runtime.h>
#include <cuda_bf16.h>
#include <math.h>

#define NN_MAX 100000
#define FG 128
#define FIN 512
#define GMAX 512
#define ZD 64
#define HID 64

// ---------------- scratch (device globals: no allocation allowed) ----------------
__device__ float g_xw  [NN_MAX * FG];   // x @ Wg
__device__ float g_agg [NN_MAX * FG];   // neighbor aggregation
__device__ float g_dinv[NN_MAX];        // 1/sqrt(deg)
__device__ float g_psum[GMAX * FG];     // pool sum
__device__ unsigned g_pmax[GMAX * FG];  // pool max (float bits, all vals >= 0)
__device__ float g_cnt [GMAX];          // nodes per graph

// ---------------- init ----------------
__global__ void k_init(int N) {
    int i = blockIdx.x * blockDim.x + threadIdx.x;
    int tot = N * FG;
    if (i < tot) g_agg[i] = 0.f;
    if (i < GMAX * FG) { g_psum[i] = 0.f; g_pmax[i] = 0u; }
    if (i < GMAX) g_cnt[i] = 0.f;
    if (i < N) g_dinv[i] = 1.0f;   // self-loop contributes 1 to degree
}

// ---------------- degree ----------------
__global__ void k_deg(const int* __restrict__ dst, int E) {
    int e = blockIdx.x * blockDim.x + threadIdx.x;
    if (e < E) atomicAdd(&g_dinv[dst[e]], 1.0f);
}

__global__ void k_rsqrt(int N) {
    int i = blockIdx.x * blockDim.x + threadIdx.x;
    if (i < N) g_dinv[i] = rsqrtf(g_dinv[i]);
}

// ---------------- TF32 tensor-core GEMM: xw = x[N,512] @ Wg[512,128] ----------------
// Block tile 128(M) x 128(N) x 32(K). 8 warps in 4(M) x 2(N) grid; warp tile 32x64.
// mma.sync.aligned.m16n8k8.row.col.f32.tf32.tf32.f32
#define BM 128
#define BN 128
#define BK 32
#define ASTRIDE 36   // (4r+c)%32 distinct for r<8,c<4 -> conflict-free frag loads
#define BSTRIDE 132  // (4k+n)%32 distinct -> conflict-free frag loads

__device__ __forceinline__ unsigned f2tf32(float v) {
    unsigned r;
    asm("cvt.rna.tf32.f32 %0, %1;" : "=r"(r) : "f"(v));
    return r;
}

__global__ __launch_bounds__(256, 2)
void k_gemm_tf32(const float* __restrict__ X, const float* __restrict__ W, int M) {
    __shared__ unsigned As[BM * ASTRIDE];   // [row][k], tf32 bits
    __shared__ unsigned Bs[BK * BSTRIDE];   // [k][n],  tf32 bits
    int tid = threadIdx.x;
    int lane = tid & 31, wid = tid >> 5;
    int warp_m = (wid & 3) * 32;       // 4 warps along M
    int warp_n = (wid >> 2) * 64;      // 2 warps along N
    int g  = lane >> 2;                // group id 0..7
    int tig = lane & 3;                // thread in group 0..3
    int block_row = blockIdx.x * BM;

    float acc[2][8][4];
#pragma unroll
    for (int m = 0; m < 2; m++)
#pragma unroll
        for (int n = 0; n < 8; n++)
#pragma unroll
            for (int c = 0; c < 4; c++) acc[m][n][c] = 0.f;

    for (int k0 = 0; k0 < FIN; k0 += BK) {
        // --- fill A tile: 128 rows x 32 k = 1024 float4; 4 per thread ---
#pragma unroll
        for (int t = 0; t < 4; t++) {
            int idx = tid + t * 256;
            int row = idx >> 3;
            int col = (idx & 7) * 4;
            int grow = block_row + row;
            float4 v = make_float4(0.f, 0.f, 0.f, 0.f);
            if (grow < M) v = *(const float4*)&X[(size_t)grow * FIN + k0 + col];
            unsigned* p = &As[row * ASTRIDE + col];
            p[0] = f2tf32(v.x); p[1] = f2tf32(v.y);
            p[2] = f2tf32(v.z); p[3] = f2tf32(v.w);
        }
        // --- fill B tile: 32 k x 128 n = 1024 float4; 4 per thread ---
#pragma unroll
        for (int t = 0; t < 4; t++) {
            int idx = tid + t * 256;
            int kr = idx >> 5;
            int c4 = (idx & 31) * 4;
            float4 v = *(const float4*)&W[(size_t)(k0 + kr) * FG + c4];
            unsigned* p = &Bs[kr * BSTRIDE + c4];
            p[0] = f2tf32(v.x); p[1] = f2tf32(v.y);
            p[2] = f2tf32(v.z); p[3] = f2tf32(v.w);
        }
        __syncthreads();

#pragma unroll
        for (int kk = 0; kk < BK; kk += 8) {
            // A fragments for the warp's two m16 tiles
            unsigned a[2][4];
#pragma unroll
            for (int m = 0; m < 2; m++) {
                int r0 = warp_m + m * 16 + g;
                a[m][0] = As[(r0    ) * ASTRIDE + kk + tig];
                a[m][1] = As[(r0 + 8) * ASTRIDE + kk + tig];
                a[m][2] = As[(r0    ) * ASTRIDE + kk + tig + 4];
                a[m][3] = As[(r0 + 8) * ASTRIDE + kk + tig + 4];
            }
            // B fragments for 8 n8 tiles
            unsigned b[8][2];
#pragma unroll
            for (int n = 0; n < 8; n++) {
                int c0 = warp_n + n * 8 + g;
                b[n][0] = Bs[(kk + tig    ) * BSTRIDE + c0];
                b[n][1] = Bs[(kk + tig + 4) * BSTRIDE + c0];
            }
#pragma unroll
            for (int m = 0; m < 2; m++)
#pragma unroll
                for (int n = 0; n < 8; n++) {
                    asm volatile(
                        "mma.sync.aligned.m16n8k8.row.col.f32.tf32.tf32.f32 "
                        "{%0,%1,%2,%3}, {%4,%5,%6,%7}, {%8,%9}, {%0,%1,%2,%3};"
                        : "+f"(acc[m][n][0]), "+f"(acc[m][n][1]),
                          "+f"(acc[m][n][2]), "+f"(acc[m][n][3])
                        : "r"(a[m][0]), "r"(a[m][1]), "r"(a[m][2]), "r"(a[m][3]),
                          "r"(b[n][0]), "r"(b[n][1]));
                }
        }
        __syncthreads();
    }

    // --- epilogue: write fragments to g_xw ---
#pragma unroll
    for (int m = 0; m < 2; m++) {
        int r0 = block_row + warp_m + m * 16 + g;
        int r1 = r0 + 8;
#pragma unroll
        for (int n = 0; n < 8; n++) {
            int col = warp_n + n * 8 + tig * 2;
            if (r0 < M) {
                float2 v0 = make_float2(acc[m][n][0], acc[m][n][1]);
                *(float2*)&g_xw[(size_t)r0 * FG + col] = v0;
            }
            if (r1 < M) {
                float2 v1 = make_float2(acc[m][n][2], acc[m][n][3]);
                *(float2*)&g_xw[(size_t)r1 * FG + col] = v1;
            }
        }
    }
}

// ---------------- edge scatter: agg[dst] += xw[src] * dinv[src]*dinv[dst] ----------------
__global__ void k_edge(const int* __restrict__ src, const int* __restrict__ dst, int E) {
    int t = blockIdx.x * blockDim.x + threadIdx.x;
    int e = t >> 5, lane = t & 31;
    if (e >= E) return;
    int s = src[e], d = dst[e];
    float w = g_dinv[s] * g_dinv[d];
    float4 v = *(const float4*)&g_xw[s * FG + lane * 4];
    float* p = &g_agg[d * FG + lane * 4];
    asm volatile("red.global.add.v4.f32 [%0], {%1,%2,%3,%4};"
                 :: "l"(p), "f"(v.x * w), "f"(v.y * w), "f"(v.z * w), "f"(v.w * w)
                 : "memory");
}

// ---------------- node finish + pooling ----------------
__global__ void k_node_pool(const int* __restrict__ batch, const float* __restrict__ bg, int N) {
    int t = blockIdx.x * blockDim.x + threadIdx.x;
    int n = t >> 5, lane = t & 31;
    if (n >= N) return;
    float di = g_dinv[n];
    float sl = di * di;               // self-loop norm
    float4 a  = *(const float4*)&g_agg[n * FG + lane * 4];
    float4 xv = *(const float4*)&g_xw[n * FG + lane * 4];
    float4 bv = *(const float4*)&bg[lane * 4];
    float v0 = fmaxf(fmaf(xv.x, sl, a.x) + bv.x, 0.f);
    float v1 = fmaxf(fmaf(xv.y, sl, a.y) + bv.y, 0.f);
    float v2 = fmaxf(fmaf(xv.z, sl, a.z) + bv.z, 0.f);
    float v3 = fmaxf(fmaf(xv.w, sl, a.w) + bv.w, 0.f);
    int b = batch[n];
    float* ps = &g_psum[b * FG + lane * 4];
    asm volatile("red.global.add.v4.f32 [%0], {%1,%2,%3,%4};"
                 :: "l"(ps), "f"(v0), "f"(v1), "f"(v2), "f"(v3) : "memory");
    int* pm = (int*)&g_pmax[b * FG + lane * 4];
    atomicMax(pm + 0, __float_as_int(v0));   // all vals >= 0: int cmp == float cmp
    atomicMax(pm + 1, __float_as_int(v1));
    atomicMax(pm + 2, __float_as_int(v2));
    atomicMax(pm + 3, __float_as_int(v3));
    if (lane == 0) atomicAdd(&g_cnt[b], 1.0f);
}

// ---------------- head: encoder/decoder MLPs, one block per graph ----------------
__device__ __forceinline__ float eluf(float x)      { return x > 0.f ? x : expm1f(x); }
__device__ __forceinline__ float softplusf(float x) { return x > 20.f ? x : log1pf(expf(x)); }

__global__ void k_head(const float* __restrict__ eps,
                       const float* __restrict__ We1, const float* __restrict__ be1,
                       const float* __restrict__ We2, const float* __restrict__ be2,
                       const float* __restrict__ We3, const float* __restrict__ be3,
                       const float* __restrict__ Wd1, const float* __restrict__ bd1,
                       const float* __restrict__ Wd2, const float* __restrict__ bd2,
                       const float* __restrict__ Wd3, const float* __restrict__ bd3,
                       float* __restrict__ out, int G) {
    __shared__ float gx[2 * FG];
    __shared__ float t1[HID], t2[HID], ml[2 * ZD], zz[ZD], dd1[HID], dd2[HID];
    int g = blockIdx.x;
    int tid = threadIdx.x;

    float cnt = fmaxf(g_cnt[g], 1.0f);
    gx[tid]      = g_psum[g * FG + tid] / cnt;           // mean pool
    gx[FG + tid] = __int_as_float(g_pmax[g * FG + tid]); // max pool
    __syncthreads();

    if (tid < HID) {
        float s = be1[tid];
#pragma unroll 8
        for (int i = 0; i < 2 * FG; i++) s = fmaf(gx[i], We1[i * HID + tid], s);
        t1[tid] = eluf(s);
    }
    __syncthreads();
    if (tid < HID) {
        float s = be2[tid];
#pragma unroll 8
        for (int i = 0; i < HID; i++) s = fmaf(t1[i], We2[i * HID + tid], s);
        t2[tid] = tanhf(s);
    }
    __syncthreads();
    {   // ml = t2 @ We3 + be3  (128 outputs)
        float s = be3[tid];
#pragma unroll 8
        for (int i = 0; i < HID; i++) s = fmaf(t2[i], We3[i * 2 * ZD + tid], s);
        ml[tid] = s;
    }
    __syncthreads();
    if (tid < ZD) {
        float mu = ml[tid];
        float sd = 1e-6f + softplusf(ml[ZD + tid]);
        float z = fmaf(eps[g * ZD + tid], sd, mu);
        zz[tid] = z;
        out[g * ZD + tid] = mu;                 // mu block
        out[G * ZD + g * ZD + tid] = sd;        // stddev block
    }
    __syncthreads();
    if (tid < HID) {
        float s = bd1[tid];
#pragma unroll 8
        for (int i = 0; i < ZD; i++) s = fmaf(zz[i], Wd1[i * HID + tid], s);
        dd1[tid] = tanhf(s);
    }
    __syncthreads();
    if (tid < HID) {
        float s = bd2[tid];
#pragma unroll 8
        for (int i = 0; i < HID; i++) s = fmaf(dd1[i], Wd2[i * HID + tid], s);
        dd2[tid] = eluf(s);
    }
    __syncthreads();
    {   // y = sigmoid(dd2 @ Wd3 + bd3), 128 outputs
        float s = bd3[tid];
#pragma unroll 8
        for (int i = 0; i < HID; i++) s = fmaf(dd2[i], Wd3[i * FG + tid], s);
        float y = 1.0f / (1.0f + expf(-s));
        y = fminf(fmaxf(y, 1e-8f), 1.0f - 1e-8f);
        out[2 * G * ZD + g * FG + tid] = y;     // y block
    }
}

// ---------------- launch ----------------
extern "C" void kernel_launch(void* const* d_in, const int* in_sizes, int n_in,
                              void* d_out, int out_size) {
    const float* x     = (const float*)d_in[0];
    const int*   ei    = (const int*)  d_in[1];
    const int*   batch = (const int*)  d_in[2];
    const float* eps   = (const float*)d_in[3];
    const float* Wg    = (const float*)d_in[4];
    const float* bg    = (const float*)d_in[5];
    const float* We1 = (const float*)d_in[6],  *be1 = (const float*)d_in[7];
    const float* We2 = (const float*)d_in[8],  *be2 = (const float*)d_in[9];
    const float* We3 = (const float*)d_in[10], *be3 = (const float*)d_in[11];
    const float* Wd1 = (const float*)d_in[12], *bd1 = (const float*)d_in[13];
    const float* Wd2 = (const float*)d_in[14], *bd2 = (const float*)d_in[15];
    const float* Wd3 = (const float*)d_in[16], *bd3 = (const float*)d_in[17];
    float* out = (float*)d_out;

    int N = in_sizes[0] / FIN;       // 100000
    int E = in_sizes[1] / 2;         // 1600000
    int G = in_sizes[3] / ZD;        // 512
    const int* src = ei;
    const int* dst = ei + E;

    k_init<<<(N * FG + 255) / 256, 256>>>(N);
    k_deg<<<(E + 255) / 256, 256>>>(dst, E);
    k_rsqrt<<<(N + 255) / 256, 256>>>(N);
    k_gemm_tf32<<<(N + BM - 1) / BM, 256>>>(x, Wg, N);
    {
        long long t = (long long)E * 32;
        k_edge<<<(int)((t + 255) / 256), 256>>>(src, dst, E);
    }
    {
        long long t = (long long)N * 32;
        k_node_pool<<<(int)((t + 255) / 256), 256>>>(batch, bg, N);
    }
    k_head<<<G, 128>>>(eps, We1, be1, We2, be2, We3, be3,
                       Wd1, bd1, Wd2, bd2, Wd3, bd3, out, G);
}

// round 4
// speedup vs baseline: 1.5996x; 1.1320x over previous
#include <cuda_runtime.h>
#include <cuda_bf16.h>
#include <math.h>

#define NN_MAX 100000
#define FG 128
#define FIN 512
#define GMAX 512
#define ZD 64
#define HID 64

// ---------------- scratch (device globals: no allocation allowed) ----------------
__device__ float g_xws [NN_MAX * FG];   // (x @ Wg) * dinv[row]  (pre-scaled for gather)
__device__ float g_agg [NN_MAX * FG];   // aggregation; seeded with xws (self-loop)
__device__ float g_dinv[NN_MAX];        // 1/sqrt(deg)
__device__ float g_psum[GMAX * FG];     // pool sum
__device__ unsigned g_pmax[GMAX * FG];  // pool max (float bits, all vals >= 0)
__device__ float g_cnt [GMAX];          // nodes per graph

// ---------------- init: MUST cover N nodes (dinv) AND GMAX*FG (pools) ----------------
__global__ void k_init(int N) {
    int i = blockIdx.x * blockDim.x + threadIdx.x;
    if (i < GMAX * FG) { g_psum[i] = 0.f; g_pmax[i] = 0u; }
    if (i < GMAX) g_cnt[i] = 0.f;
    if (i < N) g_dinv[i] = 1.0f;   // self-loop contributes 1 to degree
}

// ---------------- degree ----------------
__global__ void k_deg(const int* __restrict__ dst, int E) {
    int e = blockIdx.x * blockDim.x + threadIdx.x;
    if (e < E) atomicAdd(&g_dinv[dst[e]], 1.0f);
}

__global__ void k_rsqrt(int N) {
    int i = blockIdx.x * blockDim.x + threadIdx.x;
    if (i < N) g_dinv[i] = rsqrtf(g_dinv[i]);
}

// ---------------- TF32 tensor-core GEMM with cp.async double buffering ----------------
// xw = x[N,512] @ Wg[512,128]; epilogue scales by dinv[row], writes g_xws and g_agg.
#define BM 128
#define BN 128
#define BK 32
#define TILES (FIN / BK)
#define ASTRIDE 36   // (4r+c)%32 distinct for frag pattern -> conflict-free
#define BSTRIDE 132

__device__ __forceinline__ unsigned f2tf32(float v) {
    unsigned r;
    asm("cvt.rna.tf32.f32 %0, %1;" : "=r"(r) : "f"(v));
    return r;
}

__global__ __launch_bounds__(256, 2)
void k_gemm_tf32(const float* __restrict__ X, const float* __restrict__ W, int M) {
    __shared__ float As[2][BM * ASTRIDE];   // raw fp32
    __shared__ float Bs[2][BK * BSTRIDE];
    int tid = threadIdx.x;
    int lane = tid & 31, wid = tid >> 5;
    int warp_m = (wid & 3) * 32;       // 4 warps along M
    int warp_n = (wid >> 2) * 64;      // 2 warps along N
    int g  = lane >> 2;                // group id 0..7
    int tig = lane & 3;                // thread in group 0..3
    int block_row = blockIdx.x * BM;

    float acc[2][8][4];
#pragma unroll
    for (int m = 0; m < 2; m++)
#pragma unroll
        for (int n = 0; n < 8; n++)
#pragma unroll
            for (int c = 0; c < 4; c++) acc[m][n][c] = 0.f;

    auto load_tile = [&](int t, int b) {
        int k0 = t * BK;
#pragma unroll
        for (int i = 0; i < 4; i++) {
            int idx = tid + i * 256;
            int row = idx >> 3;
            int col = (idx & 7) * 4;
            int grow = block_row + row;
            int cg = grow < M ? grow : 0;          // clamp addr; zero-fill via src-size
            int sz = grow < M ? 16 : 0;
            const float* src = &X[(size_t)cg * FIN + k0 + col];
            unsigned d = (unsigned)__cvta_generic_to_shared(&As[b][row * ASTRIDE + col]);
            asm volatile("cp.async.cg.shared.global [%0], [%1], 16, %2;"
                         :: "r"(d), "l"(src), "r"(sz));
        }
#pragma unroll
        for (int i = 0; i < 4; i++) {
            int idx = tid + i * 256;
            int kr = idx >> 5;
            int c4 = (idx & 31) * 4;
            const float* src = &W[(size_t)(k0 + kr) * FG + c4];
            unsigned d = (unsigned)__cvta_generic_to_shared(&Bs[b][kr * BSTRIDE + c4]);
            asm volatile("cp.async.cg.shared.global [%0], [%1], 16;"
                         :: "r"(d), "l"(src));
        }
        asm volatile("cp.async.commit_group;");
    };

    load_tile(0, 0);

    int buf = 0;
    for (int t = 0; t < TILES; t++) {
        if (t + 1 < TILES) {
            load_tile(t + 1, buf ^ 1);
            asm volatile("cp.async.wait_group %0;" :: "n"(1));
        } else {
            asm volatile("cp.async.wait_group %0;" :: "n"(0));
        }
        __syncthreads();

#pragma unroll
        for (int kk = 0; kk < BK; kk += 8) {
            unsigned a[2][4];
#pragma unroll
            for (int m = 0; m < 2; m++) {
                int r0 = warp_m + m * 16 + g;
                a[m][0] = f2tf32(As[buf][(r0    ) * ASTRIDE + kk + tig]);
                a[m][1] = f2tf32(As[buf][(r0 + 8) * ASTRIDE + kk + tig]);
                a[m][2] = f2tf32(As[buf][(r0    ) * ASTRIDE + kk + tig + 4]);
                a[m][3] = f2tf32(As[buf][(r0 + 8) * ASTRIDE + kk + tig + 4]);
            }
            unsigned b[8][2];
#pragma unroll
            for (int n = 0; n < 8; n++) {
                int c0 = warp_n + n * 8 + g;
                b[n][0] = f2tf32(Bs[buf][(kk + tig    ) * BSTRIDE + c0]);
                b[n][1] = f2tf32(Bs[buf][(kk + tig + 4) * BSTRIDE + c0]);
            }
#pragma unroll
            for (int m = 0; m < 2; m++)
#pragma unroll
                for (int n = 0; n < 8; n++) {
                    asm volatile(
                        "mma.sync.aligned.m16n8k8.row.col.f32.tf32.tf32.f32 "
                        "{%0,%1,%2,%3}, {%4,%5,%6,%7}, {%8,%9}, {%0,%1,%2,%3};"
                        : "+f"(acc[m][n][0]), "+f"(acc[m][n][1]),
                          "+f"(acc[m][n][2]), "+f"(acc[m][n][3])
                        : "r"(a[m][0]), "r"(a[m][1]), "r"(a[m][2]), "r"(a[m][3]),
                          "r"(b[n][0]), "r"(b[n][1]));
                }
        }
        __syncthreads();
        buf ^= 1;
    }

    // --- epilogue: scale by dinv[row]; write g_xws and seed g_agg (self-loop) ---
#pragma unroll
    for (int m = 0; m < 2; m++) {
        int r0 = block_row + warp_m + m * 16 + g;
        int r1 = r0 + 8;
        float d0 = (r0 < M) ? g_dinv[r0] : 0.f;
        float d1 = (r1 < M) ? g_dinv[r1] : 0.f;
#pragma unroll
        for (int n = 0; n < 8; n++) {
            int col = warp_n + n * 8 + tig * 2;
            if (r0 < M) {
                float2 v0 = make_float2(acc[m][n][0] * d0, acc[m][n][1] * d0);
                *(float2*)&g_xws[(size_t)r0 * FG + col] = v0;
                *(float2*)&g_agg[(size_t)r0 * FG + col] = v0;
            }
            if (r1 < M) {
                float2 v1 = make_float2(acc[m][n][2] * d1, acc[m][n][3] * d1);
                *(float2*)&g_xws[(size_t)r1 * FG + col] = v1;
                *(float2*)&g_agg[(size_t)r1 * FG + col] = v1;
            }
        }
    }
}

// ---------------- edge scatter: agg[dst] += xws[src]  (pure gather + red) ----------------
__global__ void k_edge(const int* __restrict__ src, const int* __restrict__ dst, int E) {
    int t = blockIdx.x * blockDim.x + threadIdx.x;
    int e = t >> 5, lane = t & 31;
    if (e >= E) return;
    int s = src[e], d = dst[e];
    float4 v = *(const float4*)&g_xws[(size_t)s * FG + lane * 4];
    float* p = &g_agg[(size_t)d * FG + lane * 4];
    asm volatile("red.global.add.v4.f32 [%0], {%1,%2,%3,%4};"
                 :: "l"(p), "f"(v.x), "f"(v.y), "f"(v.z), "f"(v.w) : "memory");
}

// ---------------- node finish + pooling: val = relu(agg*dinv + bg) ----------------
__global__ void k_node_pool(const int* __restrict__ batch, const float* __restrict__ bg, int N) {
    int t = blockIdx.x * blockDim.x + threadIdx.x;
    int n = t >> 5, lane = t & 31;
    if (n >= N) return;
    float di = g_dinv[n];
    float4 a  = *(const float4*)&g_agg[(size_t)n * FG + lane * 4];
    float4 bv = *(const float4*)&bg[lane * 4];
    float v0 = fmaxf(fmaf(a.x, di, bv.x), 0.f);
    float v1 = fmaxf(fmaf(a.y, di, bv.y), 0.f);
    float v2 = fmaxf(fmaf(a.z, di, bv.z), 0.f);
    float v3 = fmaxf(fmaf(a.w, di, bv.w), 0.f);
    int b = batch[n];
    float* ps = &g_psum[b * FG + lane * 4];
    asm volatile("red.global.add.v4.f32 [%0], {%1,%2,%3,%4};"
                 :: "l"(ps), "f"(v0), "f"(v1), "f"(v2), "f"(v3) : "memory");
    int* pm = (int*)&g_pmax[b * FG + lane * 4];
    atomicMax(pm + 0, __float_as_int(v0));   // all vals >= 0: int cmp == float cmp
    atomicMax(pm + 1, __float_as_int(v1));
    atomicMax(pm + 2, __float_as_int(v2));
    atomicMax(pm + 3, __float_as_int(v3));
    if (lane == 0) atomicAdd(&g_cnt[b], 1.0f);
}

// ---------------- head: encoder/decoder MLPs, one block per graph ----------------
__device__ __forceinline__ float eluf(float x)      { return x > 0.f ? x : expm1f(x); }
__device__ __forceinline__ float softplusf(float x) { return x > 20.f ? x : log1pf(expf(x)); }

__global__ void k_head(const float* __restrict__ eps,
                       const float* __restrict__ We1, const float* __restrict__ be1,
                       const float* __restrict__ We2, const float* __restrict__ be2,
                       const float* __restrict__ We3, const float* __restrict__ be3,
                       const float* __restrict__ Wd1, const float* __restrict__ bd1,
                       const float* __restrict__ Wd2, const float* __restrict__ bd2,
                       const float* __restrict__ Wd3, const float* __restrict__ bd3,
                       float* __restrict__ out, int G) {
    __shared__ float gx[2 * FG];
    __shared__ float t1[HID], t2[HID], ml[2 * ZD], zz[ZD], dd1[HID], dd2[HID];
    int g = blockIdx.x;
    int tid = threadIdx.x;

    float cnt = fmaxf(g_cnt[g], 1.0f);
    gx[tid]      = g_psum[g * FG + tid] / cnt;           // mean pool
    gx[FG + tid] = __int_as_float(g_pmax[g * FG + tid]); // max pool
    __syncthreads();

    if (tid < HID) {
        float s = be1[tid];
#pragma unroll 8
        for (int i = 0; i < 2 * FG; i++) s = fmaf(gx[i], We1[i * HID + tid], s);
        t1[tid] = eluf(s);
    }
    __syncthreads();
    if (tid < HID) {
        float s = be2[tid];
#pragma unroll 8
        for (int i = 0; i < HID; i++) s = fmaf(t1[i], We2[i * HID + tid], s);
        t2[tid] = tanhf(s);
    }
    __syncthreads();
    {   // ml = t2 @ We3 + be3  (128 outputs)
        float s = be3[tid];
#pragma unroll 8
        for (int i = 0; i < HID; i++) s = fmaf(t2[i], We3[i * 2 * ZD + tid], s);
        ml[tid] = s;
    }
    __syncthreads();
    if (tid < ZD) {
        float mu = ml[tid];
        float sd = 1e-6f + softplusf(ml[ZD + tid]);
        float z = fmaf(eps[g * ZD + tid], sd, mu);
        zz[tid] = z;
        out[g * ZD + tid] = mu;                 // mu block
        out[G * ZD + g * ZD + tid] = sd;        // stddev block
    }
    __syncthreads();
    if (tid < HID) {
        float s = bd1[tid];
#pragma unroll 8
        for (int i = 0; i < ZD; i++) s = fmaf(zz[i], Wd1[i * HID + tid], s);
        dd1[tid] = tanhf(s);
    }
    __syncthreads();
    if (tid < HID) {
        float s = bd2[tid];
#pragma unroll 8
        for (int i = 0; i < HID; i++) s = fmaf(dd1[i], Wd2[i * HID + tid], s);
        dd2[tid] = eluf(s);
    }
    __syncthreads();
    {   // y = sigmoid(dd2 @ Wd3 + bd3), 128 outputs
        float s = bd3[tid];
#pragma unroll 8
        for (int i = 0; i < HID; i++) s = fmaf(dd2[i], Wd3[i * FG + tid], s);
        float y = 1.0f / (1.0f + expf(-s));
        y = fminf(fmaxf(y, 1e-8f), 1.0f - 1e-8f);
        out[2 * G * ZD + g * FG + tid] = y;     // y block
    }
}

// ---------------- launch ----------------
extern "C" void kernel_launch(void* const* d_in, const int* in_sizes, int n_in,
                              void* d_out, int out_size) {
    const float* x     = (const float*)d_in[0];
    const int*   ei    = (const int*)  d_in[1];
    const int*   batch = (const int*)  d_in[2];
    const float* eps   = (const float*)d_in[3];
    const float* Wg    = (const float*)d_in[4];
    const float* bg    = (const float*)d_in[5];
    const float* We1 = (const float*)d_in[6],  *be1 = (const float*)d_in[7];
    const float* We2 = (const float*)d_in[8],  *be2 = (const float*)d_in[9];
    const float* We3 = (const float*)d_in[10], *be3 = (const float*)d_in[11];
    const float* Wd1 = (const float*)d_in[12], *bd1 = (const float*)d_in[13];
    const float* Wd2 = (const float*)d_in[14], *bd2 = (const float*)d_in[15];
    const float* Wd3 = (const float*)d_in[16], *bd3 = (const float*)d_in[17];
    float* out = (float*)d_out;

    int N = in_sizes[0] / FIN;       // 100000
    int E = in_sizes[1] / 2;         // 1600000
    int G = in_sizes[3] / ZD;        // 512
    const int* src = ei;
    const int* dst = ei + E;

    // init grid must cover BOTH N (dinv seeds) and GMAX*FG (pool arrays)
    int init_n = N > GMAX * FG ? N : GMAX * FG;
    k_init<<<(init_n + 255) / 256, 256>>>(N);
    k_deg<<<(E + 255) / 256, 256>>>(dst, E);
    k_rsqrt<<<(N + 255) / 256, 256>>>(N);
    k_gemm_tf32<<<(N + BM - 1) / BM, 256>>>(x, Wg, N);
    {
        long long t = (long long)E * 32;
        k_edge<<<(int)((t + 255) / 256), 256>>>(src, dst, E);
    }
    {
        long long t = (long long)N * 32;
        k_node_pool<<<(int)((t + 255) / 256), 256>>>(batch, bg, N);
    }
    k_head<<<G, 128>>>(eps, We1, be1, We2, be2, We3, be3,
                       Wd1, bd1, Wd2, bd2, Wd3, bd3, out, G);
}

// round 5
// speedup vs baseline: 1.6523x; 1.0329x over previous
#include <cuda_runtime.h>
#include <cuda_bf16.h>
#include <math.h>

#define NN_MAX 100000
#define NE_MAX 1600000
#define FG 128
#define FIN 512
#define GMAX 512
#define ZD 64
#define HID 64
#define SCAN_BLK 512
#define MAX_NB 256          // ceil(NN_MAX / SCAN_BLK) = 196 <= 256

// ---------------- scratch (device globals) ----------------
__device__ float g_xws [NN_MAX * FG];   // (x @ Wg) * dinv[row]
__device__ float g_dinv[NN_MAX];        // 1/sqrt(deg)
__device__ int   g_icnt[NN_MAX];        // in-degree (excl self loop)
__device__ int   g_rowptr[NN_MAX];      // CSR row starts (exclusive scan of icnt)
__device__ int   g_cur [NN_MAX];        // fill cursors
__device__ int   g_csr [NE_MAX];        // src node per CSR slot
__device__ int   g_bsum[MAX_NB];        // scan block sums
__device__ float g_psum[GMAX * FG];     // pool sum
__device__ unsigned g_pmax[GMAX * FG];  // pool max (float bits, vals >= 0)
__device__ float g_cnt [GMAX];          // nodes per graph

// ---------------- init ----------------
__global__ void k_init(int N) {
    int i = blockIdx.x * blockDim.x + threadIdx.x;
    if (i < GMAX * FG) { g_psum[i] = 0.f; g_pmax[i] = 0u; }
    if (i < GMAX) g_cnt[i] = 0.f;
    if (i < N) g_icnt[i] = 0;
}

// ---------------- degree histogram ----------------
__global__ void k_deg(const int* __restrict__ dst, int E) {
    int e = blockIdx.x * blockDim.x + threadIdx.x;
    if (e < E) atomicAdd(&g_icnt[dst[e]], 1);
}

__global__ void k_dinv(int N) {
    int i = blockIdx.x * blockDim.x + threadIdx.x;
    if (i < N) g_dinv[i] = rsqrtf((float)(g_icnt[i] + 1));   // +1 self loop
}

// ---------------- exclusive scan of icnt -> rowptr (3 kernels) ----------------
__global__ void k_scan1(int N) {
    __shared__ int sh[SCAN_BLK];
    int tid = threadIdx.x;
    int i = blockIdx.x * SCAN_BLK + tid;
    int v = (i < N) ? g_icnt[i] : 0;
    sh[tid] = v;
    __syncthreads();
#pragma unroll
    for (int off = 1; off < SCAN_BLK; off <<= 1) {
        int t = (tid >= off) ? sh[tid - off] : 0;
        __syncthreads();
        sh[tid] += t;
        __syncthreads();
    }
    if (i < N) g_rowptr[i] = sh[tid] - v;     // exclusive
    if (tid == SCAN_BLK - 1) g_bsum[blockIdx.x] = sh[tid];
}

__global__ void k_scan2(int nb) {
    __shared__ int sh[MAX_NB];
    int tid = threadIdx.x;
    int v = (tid < nb) ? g_bsum[tid] : 0;
    sh[tid] = v;
    __syncthreads();
#pragma unroll
    for (int off = 1; off < MAX_NB; off <<= 1) {
        int t = (tid >= off) ? sh[tid - off] : 0;
        __syncthreads();
        sh[tid] += t;
        __syncthreads();
    }
    if (tid < nb) g_bsum[tid] = sh[tid] - v;  // exclusive
}

__global__ void k_scan3(int N) {
    int i = blockIdx.x * blockDim.x + threadIdx.x;
    if (i < N) {
        int r = g_rowptr[i] + g_bsum[i / SCAN_BLK];
        g_rowptr[i] = r;
        g_cur[i] = r;
    }
}

// ---------------- CSR fill ----------------
__global__ void k_fill(const int* __restrict__ src, const int* __restrict__ dst, int E) {
    int e = blockIdx.x * blockDim.x + threadIdx.x;
    if (e < E) {
        int pos = atomicAdd(&g_cur[dst[e]], 1);
        g_csr[pos] = src[e];
    }
}

// ---------------- TF32 tensor-core GEMM with cp.async double buffering ----------------
#define BM 128
#define BN 128
#define BK 32
#define TILES (FIN / BK)
#define ASTRIDE 36
#define BSTRIDE 132

__device__ __forceinline__ unsigned f2tf32(float v) {
    unsigned r;
    asm("cvt.rna.tf32.f32 %0, %1;" : "=r"(r) : "f"(v));
    return r;
}

__global__ __launch_bounds__(256, 2)
void k_gemm_tf32(const float* __restrict__ X, const float* __restrict__ W, int M) {
    __shared__ float As[2][BM * ASTRIDE];
    __shared__ float Bs[2][BK * BSTRIDE];
    int tid = threadIdx.x;
    int lane = tid & 31, wid = tid >> 5;
    int warp_m = (wid & 3) * 32;
    int warp_n = (wid >> 2) * 64;
    int g  = lane >> 2;
    int tig = lane & 3;
    int block_row = blockIdx.x * BM;

    float acc[2][8][4];
#pragma unroll
    for (int m = 0; m < 2; m++)
#pragma unroll
        for (int n = 0; n < 8; n++)
#pragma unroll
            for (int c = 0; c < 4; c++) acc[m][n][c] = 0.f;

    auto load_tile = [&](int t, int b) {
        int k0 = t * BK;
#pragma unroll
        for (int i = 0; i < 4; i++) {
            int idx = tid + i * 256;
            int row = idx >> 3;
            int col = (idx & 7) * 4;
            int grow = block_row + row;
            int cg = grow < M ? grow : 0;
            int sz = grow < M ? 16 : 0;
            const float* src = &X[(size_t)cg * FIN + k0 + col];
            unsigned d = (unsigned)__cvta_generic_to_shared(&As[b][row * ASTRIDE + col]);
            asm volatile("cp.async.cg.shared.global [%0], [%1], 16, %2;"
                         :: "r"(d), "l"(src), "r"(sz));
        }
#pragma unroll
        for (int i = 0; i < 4; i++) {
            int idx = tid + i * 256;
            int kr = idx >> 5;
            int c4 = (idx & 31) * 4;
            const float* src = &W[(size_t)(k0 + kr) * FG + c4];
            unsigned d = (unsigned)__cvta_generic_to_shared(&Bs[b][kr * BSTRIDE + c4]);
            asm volatile("cp.async.cg.shared.global [%0], [%1], 16;"
                         :: "r"(d), "l"(src));
        }
        asm volatile("cp.async.commit_group;");
    };

    load_tile(0, 0);

    int buf = 0;
    for (int t = 0; t < TILES; t++) {
        if (t + 1 < TILES) {
            load_tile(t + 1, buf ^ 1);
            asm volatile("cp.async.wait_group %0;" :: "n"(1));
        } else {
            asm volatile("cp.async.wait_group %0;" :: "n"(0));
        }
        __syncthreads();

#pragma unroll
        for (int kk = 0; kk < BK; kk += 8) {
            unsigned a[2][4];
#pragma unroll
            for (int m = 0; m < 2; m++) {
                int r0 = warp_m + m * 16 + g;
                a[m][0] = f2tf32(As[buf][(r0    ) * ASTRIDE + kk + tig]);
                a[m][1] = f2tf32(As[buf][(r0 + 8) * ASTRIDE + kk + tig]);
                a[m][2] = f2tf32(As[buf][(r0    ) * ASTRIDE + kk + tig + 4]);
                a[m][3] = f2tf32(As[buf][(r0 + 8) * ASTRIDE + kk + tig + 4]);
            }
            unsigned b[8][2];
#pragma unroll
            for (int n = 0; n < 8; n++) {
                int c0 = warp_n + n * 8 + g;
                b[n][0] = f2tf32(Bs[buf][(kk + tig    ) * BSTRIDE + c0]);
                b[n][1] = f2tf32(Bs[buf][(kk + tig + 4) * BSTRIDE + c0]);
            }
#pragma unroll
            for (int m = 0; m < 2; m++)
#pragma unroll
                for (int n = 0; n < 8; n++) {
                    asm volatile(
                        "mma.sync.aligned.m16n8k8.row.col.f32.tf32.tf32.f32 "
                        "{%0,%1,%2,%3}, {%4,%5,%6,%7}, {%8,%9}, {%0,%1,%2,%3};"
                        : "+f"(acc[m][n][0]), "+f"(acc[m][n][1]),
                          "+f"(acc[m][n][2]), "+f"(acc[m][n][3])
                        : "r"(a[m][0]), "r"(a[m][1]), "r"(a[m][2]), "r"(a[m][3]),
                          "r"(b[n][0]), "r"(b[n][1]));
                }
        }
        __syncthreads();
        buf ^= 1;
    }

    // epilogue: write g_xws scaled by dinv[row] only (no agg seed needed)
#pragma unroll
    for (int m = 0; m < 2; m++) {
        int r0 = block_row + warp_m + m * 16 + g;
        int r1 = r0 + 8;
        float d0 = (r0 < M) ? g_dinv[r0] : 0.f;
        float d1 = (r1 < M) ? g_dinv[r1] : 0.f;
#pragma unroll
        for (int n = 0; n < 8; n++) {
            int col = warp_n + n * 8 + tig * 2;
            if (r0 < M)
                *(float2*)&g_xws[(size_t)r0 * FG + col] =
                    make_float2(acc[m][n][0] * d0, acc[m][n][1] * d0);
            if (r1 < M)
                *(float2*)&g_xws[(size_t)r1 * FG + col] =
                    make_float2(acc[m][n][2] * d1, acc[m][n][3] * d1);
        }
    }
}

// ---------------- fused gather + node finish + pooling (no atomics on features) ----------------
__global__ void k_gather_pool(const int* __restrict__ batch, const float* __restrict__ bg, int N) {
    int t = blockIdx.x * blockDim.x + threadIdx.x;
    int n = t >> 5, lane = t & 31;
    if (n >= N) return;
    int c4 = lane * 4;
    // self-loop term
    float4 acc = *(const float4*)&g_xws[(size_t)n * FG + c4];
    int start = g_rowptr[n];
    int cnt   = g_icnt[n];
    int e = 0;
    for (; e + 4 <= cnt; e += 4) {
        int s0 = g_csr[start + e    ];
        int s1 = g_csr[start + e + 1];
        int s2 = g_csr[start + e + 2];
        int s3 = g_csr[start + e + 3];
        float4 v0 = *(const float4*)&g_xws[(size_t)s0 * FG + c4];
        float4 v1 = *(const float4*)&g_xws[(size_t)s1 * FG + c4];
        float4 v2 = *(const float4*)&g_xws[(size_t)s2 * FG + c4];
        float4 v3 = *(const float4*)&g_xws[(size_t)s3 * FG + c4];
        acc.x += v0.x + v1.x + v2.x + v3.x;
        acc.y += v0.y + v1.y + v2.y + v3.y;
        acc.z += v0.z + v1.z + v2.z + v3.z;
        acc.w += v0.w + v1.w + v2.w + v3.w;
    }
    for (; e < cnt; e++) {
        int s = g_csr[start + e];
        float4 v = *(const float4*)&g_xws[(size_t)s * FG + c4];
        acc.x += v.x; acc.y += v.y; acc.z += v.z; acc.w += v.w;
    }
    float di = g_dinv[n];
    float4 bv = *(const float4*)&bg[c4];
    float v0 = fmaxf(fmaf(acc.x, di, bv.x), 0.f);
    float v1 = fmaxf(fmaf(acc.y, di, bv.y), 0.f);
    float v2 = fmaxf(fmaf(acc.z, di, bv.z), 0.f);
    float v3 = fmaxf(fmaf(acc.w, di, bv.w), 0.f);
    int b = batch[n];
    float* ps = &g_psum[b * FG + c4];
    asm volatile("red.global.add.v4.f32 [%0], {%1,%2,%3,%4};"
                 :: "l"(ps), "f"(v0), "f"(v1), "f"(v2), "f"(v3) : "memory");
    int* pm = (int*)&g_pmax[b * FG + c4];
    atomicMax(pm + 0, __float_as_int(v0));
    atomicMax(pm + 1, __float_as_int(v1));
    atomicMax(pm + 2, __float_as_int(v2));
    atomicMax(pm + 3, __float_as_int(v3));
    if (lane == 0) atomicAdd(&g_cnt[b], 1.0f);
}

// ---------------- head: encoder/decoder MLPs ----------------
__device__ __forceinline__ float eluf(float x)      { return x > 0.f ? x : expm1f(x); }
__device__ __forceinline__ float softplusf(float x) { return x > 20.f ? x : log1pf(expf(x)); }

__global__ void k_head(const float* __restrict__ eps,
                       const float* __restrict__ We1, const float* __restrict__ be1,
                       const float* __restrict__ We2, const float* __restrict__ be2,
                       const float* __restrict__ We3, const float* __restrict__ be3,
                       const float* __restrict__ Wd1, const float* __restrict__ bd1,
                       const float* __restrict__ Wd2, const float* __restrict__ bd2,
                       const float* __restrict__ Wd3, const float* __restrict__ bd3,
                       float* __restrict__ out, int G) {
    __shared__ float gx[2 * FG];
    __shared__ float t1[HID], t2[HID], ml[2 * ZD], zz[ZD], dd1[HID], dd2[HID];
    int g = blockIdx.x;
    int tid = threadIdx.x;

    float cnt = fmaxf(g_cnt[g], 1.0f);
    gx[tid]      = g_psum[g * FG + tid] / cnt;
    gx[FG + tid] = __int_as_float(g_pmax[g * FG + tid]);
    __syncthreads();

    if (tid < HID) {
        float s = be1[tid];
#pragma unroll 8
        for (int i = 0; i < 2 * FG; i++) s = fmaf(gx[i], We1[i * HID + tid], s);
        t1[tid] = eluf(s);
    }
    __syncthreads();
    if (tid < HID) {
        float s = be2[tid];
#pragma unroll 8
        for (int i = 0; i < HID; i++) s = fmaf(t1[i], We2[i * HID + tid], s);
        t2[tid] = tanhf(s);
    }
    __syncthreads();
    {
        float s = be3[tid];
#pragma unroll 8
        for (int i = 0; i < HID; i++) s = fmaf(t2[i], We3[i * 2 * ZD + tid], s);
        ml[tid] = s;
    }
    __syncthreads();
    if (tid < ZD) {
        float mu = ml[tid];
        float sd = 1e-6f + softplusf(ml[ZD + tid]);
        float z = fmaf(eps[g * ZD + tid], sd, mu);
        zz[tid] = z;
        out[g * ZD + tid] = mu;
        out[G * ZD + g * ZD + tid] = sd;
    }
    __syncthreads();
    if (tid < HID) {
        float s = bd1[tid];
#pragma unroll 8
        for (int i = 0; i < ZD; i++) s = fmaf(zz[i], Wd1[i * HID + tid], s);
        dd1[tid] = tanhf(s);
    }
    __syncthreads();
    if (tid < HID) {
        float s = bd2[tid];
#pragma unroll 8
        for (int i = 0; i < HID; i++) s = fmaf(dd1[i], Wd2[i * HID + tid], s);
        dd2[tid] = eluf(s);
    }
    __syncthreads();
    {
        float s = bd3[tid];
#pragma unroll 8
        for (int i = 0; i < HID; i++) s = fmaf(dd2[i], Wd3[i * FG + tid], s);
        float y = 1.0f / (1.0f + expf(-s));
        y = fminf(fmaxf(y, 1e-8f), 1.0f - 1e-8f);
        out[2 * G * ZD + g * FG + tid] = y;
    }
}

// ---------------- launch ----------------
extern "C" void kernel_launch(void* const* d_in, const int* in_sizes, int n_in,
                              void* d_out, int out_size) {
    const float* x     = (const float*)d_in[0];
    const int*   ei    = (const int*)  d_in[1];
    const int*   batch = (const int*)  d_in[2];
    const float* eps   = (const float*)d_in[3];
    const float* Wg    = (const float*)d_in[4];
    const float* bg    = (const float*)d_in[5];
    const float* We1 = (const float*)d_in[6],  *be1 = (const float*)d_in[7];
    const float* We2 = (const float*)d_in[8],  *be2 = (const float*)d_in[9];
    const float* We3 = (const float*)d_in[10], *be3 = (const float*)d_in[11];
    const float* Wd1 = (const float*)d_in[12], *bd1 = (const float*)d_in[13];
    const float* Wd2 = (const float*)d_in[14], *bd2 = (const float*)d_in[15];
    const float* Wd3 = (const float*)d_in[16], *bd3 = (const float*)d_in[17];
    float* out = (float*)d_out;

    int N = in_sizes[0] / FIN;       // 100000
    int E = in_sizes[1] / 2;         // 1600000
    int G = in_sizes[3] / ZD;        // 512
    const int* src = ei;
    const int* dst = ei + E;
    int nb = (N + SCAN_BLK - 1) / SCAN_BLK;   // 196

    int init_n = N > GMAX * FG ? N : GMAX * FG;
    k_init<<<(init_n + 255) / 256, 256>>>(N);
    k_deg<<<(E + 255) / 256, 256>>>(dst, E);
    k_dinv<<<(N + 255) / 256, 256>>>(N);
    k_scan1<<<nb, SCAN_BLK>>>(N);
    k_scan2<<<1, MAX_NB>>>(nb);
    k_scan3<<<(N + 255) / 256, 256>>>(N);
    k_fill<<<(E + 255) / 256, 256>>>(src, dst, E);
    k_gemm_tf32<<<(N + BM - 1) / BM, 256>>>(x, Wg, N);
    {
        long long t = (long long)N * 32;
        k_gather_pool<<<(int)((t + 255) / 256), 256>>>(batch, bg, N);
    }
    k_head<<<G, 128>>>(eps, We1, be1, We2, be2, We3, be3,
                       Wd1, bd1, Wd2, bd2, Wd3, bd3, out, G);
}

// round 6
// speedup vs baseline: 2.4929x; 1.5088x over previous
#include <cuda_runtime.h>
#include <cuda_bf16.h>
#include <math.h>

#define NN_MAX 100000
#define NE_MAX 1600000
#define FG 128
#define FIN 512
#define GMAX 512
#define ZD 64
#define HID 64
#define SCAN_BLK 512
#define MAX_NB 256          // ceil(NN_MAX / SCAN_BLK) = 196 <= 256
#define NODES_PER_WARP 32

// ---------------- scratch (device globals) ----------------
__device__ float g_xws [NN_MAX * FG];   // (x @ Wg) * dinv[row]
__device__ float g_dinv[NN_MAX];        // 1/sqrt(deg)
__device__ int   g_icnt[NN_MAX];        // in-degree (excl self loop)
__device__ int   g_rowptr[NN_MAX];      // CSR row starts
__device__ int   g_cur [NN_MAX];        // fill cursors
__device__ int   g_csr [NE_MAX];        // src node per CSR slot
__device__ int   g_bsum[MAX_NB];        // scan block sums
__device__ float g_psum[GMAX * FG];     // pool sum
__device__ unsigned g_pmax[GMAX * FG];  // pool max (float bits, vals >= 0)
__device__ float g_cnt [GMAX];          // nodes per graph

// ---------------- init ----------------
__global__ void k_init(int N) {
    int i = blockIdx.x * blockDim.x + threadIdx.x;
    if (i < GMAX * FG) { g_psum[i] = 0.f; g_pmax[i] = 0u; }
    if (i < GMAX) g_cnt[i] = 0.f;
    if (i < N) g_icnt[i] = 0;
}

// ---------------- degree histogram ----------------
__global__ void k_deg(const int* __restrict__ dst, int E) {
    int e = blockIdx.x * blockDim.x + threadIdx.x;
    if (e < E) atomicAdd(&g_icnt[dst[e]], 1);
}

__global__ void k_dinv(int N) {
    int i = blockIdx.x * blockDim.x + threadIdx.x;
    if (i < N) g_dinv[i] = rsqrtf((float)(g_icnt[i] + 1));   // +1 self loop
}

// ---------------- exclusive scan of icnt -> rowptr ----------------
__global__ void k_scan1(int N) {
    __shared__ int sh[SCAN_BLK];
    int tid = threadIdx.x;
    int i = blockIdx.x * SCAN_BLK + tid;
    int v = (i < N) ? g_icnt[i] : 0;
    sh[tid] = v;
    __syncthreads();
#pragma unroll
    for (int off = 1; off < SCAN_BLK; off <<= 1) {
        int t = (tid >= off) ? sh[tid - off] : 0;
        __syncthreads();
        sh[tid] += t;
        __syncthreads();
    }
    if (i < N) g_rowptr[i] = sh[tid] - v;
    if (tid == SCAN_BLK - 1) g_bsum[blockIdx.x] = sh[tid];
}

__global__ void k_scan2(int nb) {
    __shared__ int sh[MAX_NB];
    int tid = threadIdx.x;
    int v = (tid < nb) ? g_bsum[tid] : 0;
    sh[tid] = v;
    __syncthreads();
#pragma unroll
    for (int off = 1; off < MAX_NB; off <<= 1) {
        int t = (tid >= off) ? sh[tid - off] : 0;
        __syncthreads();
        sh[tid] += t;
        __syncthreads();
    }
    if (tid < nb) g_bsum[tid] = sh[tid] - v;
}

__global__ void k_scan3(int N) {
    int i = blockIdx.x * blockDim.x + threadIdx.x;
    if (i < N) {
        int r = g_rowptr[i] + g_bsum[i / SCAN_BLK];
        g_rowptr[i] = r;
        g_cur[i] = r;
    }
}

// ---------------- CSR fill ----------------
__global__ void k_fill(const int* __restrict__ src, const int* __restrict__ dst, int E) {
    int e = blockIdx.x * blockDim.x + threadIdx.x;
    if (e < E) {
        int pos = atomicAdd(&g_cur[dst[e]], 1);
        g_csr[pos] = src[e];
    }
}

// ---------------- TF32 tensor-core GEMM with cp.async double buffering ----------------
#define BM 128
#define BN 128
#define BK 32
#define TILES (FIN / BK)
#define ASTRIDE 36
#define BSTRIDE 132

__device__ __forceinline__ unsigned f2tf32(float v) {
    unsigned r;
    asm("cvt.rna.tf32.f32 %0, %1;" : "=r"(r) : "f"(v));
    return r;
}

__global__ __launch_bounds__(256, 2)
void k_gemm_tf32(const float* __restrict__ X, const float* __restrict__ W, int M) {
    __shared__ float As[2][BM * ASTRIDE];
    __shared__ float Bs[2][BK * BSTRIDE];
    int tid = threadIdx.x;
    int lane = tid & 31, wid = tid >> 5;
    int warp_m = (wid & 3) * 32;
    int warp_n = (wid >> 2) * 64;
    int g  = lane >> 2;
    int tig = lane & 3;
    int block_row = blockIdx.x * BM;

    float acc[2][8][4];
#pragma unroll
    for (int m = 0; m < 2; m++)
#pragma unroll
        for (int n = 0; n < 8; n++)
#pragma unroll
            for (int c = 0; c < 4; c++) acc[m][n][c] = 0.f;

    auto load_tile = [&](int t, int b) {
        int k0 = t * BK;
#pragma unroll
        for (int i = 0; i < 4; i++) {
            int idx = tid + i * 256;
            int row = idx >> 3;
            int col = (idx & 7) * 4;
            int grow = block_row + row;
            int cg = grow < M ? grow : 0;
            int sz = grow < M ? 16 : 0;
            const float* src = &X[(size_t)cg * FIN + k0 + col];
            unsigned d = (unsigned)__cvta_generic_to_shared(&As[b][row * ASTRIDE + col]);
            asm volatile("cp.async.cg.shared.global [%0], [%1], 16, %2;"
                         :: "r"(d), "l"(src), "r"(sz));
        }
#pragma unroll
        for (int i = 0; i < 4; i++) {
            int idx = tid + i * 256;
            int kr = idx >> 5;
            int c4 = (idx & 31) * 4;
            const float* src = &W[(size_t)(k0 + kr) * FG + c4];
            unsigned d = (unsigned)__cvta_generic_to_shared(&Bs[b][kr * BSTRIDE + c4]);
            asm volatile("cp.async.cg.shared.global [%0], [%1], 16;"
                         :: "r"(d), "l"(src));
        }
        asm volatile("cp.async.commit_group;");
    };

    load_tile(0, 0);

    int buf = 0;
    for (int t = 0; t < TILES; t++) {
        if (t + 1 < TILES) {
            load_tile(t + 1, buf ^ 1);
            asm volatile("cp.async.wait_group %0;" :: "n"(1));
        } else {
            asm volatile("cp.async.wait_group %0;" :: "n"(0));
        }
        __syncthreads();

#pragma unroll
        for (int kk = 0; kk < BK; kk += 8) {
            unsigned a[2][4];
#pragma unroll
            for (int m = 0; m < 2; m++) {
                int r0 = warp_m + m * 16 + g;
                a[m][0] = f2tf32(As[buf][(r0    ) * ASTRIDE + kk + tig]);
                a[m][1] = f2tf32(As[buf][(r0 + 8) * ASTRIDE + kk + tig]);
                a[m][2] = f2tf32(As[buf][(r0    ) * ASTRIDE + kk + tig + 4]);
                a[m][3] = f2tf32(As[buf][(r0 + 8) * ASTRIDE + kk + tig + 4]);
            }
            unsigned b[8][2];
#pragma unroll
            for (int n = 0; n < 8; n++) {
                int c0 = warp_n + n * 8 + g;
                b[n][0] = f2tf32(Bs[buf][(kk + tig    ) * BSTRIDE + c0]);
                b[n][1] = f2tf32(Bs[buf][(kk + tig + 4) * BSTRIDE + c0]);
            }
#pragma unroll
            for (int m = 0; m < 2; m++)
#pragma unroll
                for (int n = 0; n < 8; n++) {
                    asm volatile(
                        "mma.sync.aligned.m16n8k8.row.col.f32.tf32.tf32.f32 "
                        "{%0,%1,%2,%3}, {%4,%5,%6,%7}, {%8,%9}, {%0,%1,%2,%3};"
                        : "+f"(acc[m][n][0]), "+f"(acc[m][n][1]),
                          "+f"(acc[m][n][2]), "+f"(acc[m][n][3])
                        : "r"(a[m][0]), "r"(a[m][1]), "r"(a[m][2]), "r"(a[m][3]),
                          "r"(b[n][0]), "r"(b[n][1]));
                }
        }
        __syncthreads();
        buf ^= 1;
    }

#pragma unroll
    for (int m = 0; m < 2; m++) {
        int r0 = block_row + warp_m + m * 16 + g;
        int r1 = r0 + 8;
        float d0 = (r0 < M) ? g_dinv[r0] : 0.f;
        float d1 = (r1 < M) ? g_dinv[r1] : 0.f;
#pragma unroll
        for (int n = 0; n < 8; n++) {
            int col = warp_n + n * 8 + tig * 2;
            if (r0 < M)
                *(float2*)&g_xws[(size_t)r0 * FG + col] =
                    make_float2(acc[m][n][0] * d0, acc[m][n][1] * d0);
            if (r1 < M)
                *(float2*)&g_xws[(size_t)r1 * FG + col] =
                    make_float2(acc[m][n][2] * d1, acc[m][n][3] * d1);
        }
    }
}

// ---- gather + pooling with register-resident segmented reduction ----
// One warp handles NODES_PER_WARP consecutive nodes (batch is sorted), keeps
// running sum/max in registers, flushes atomics only on graph change / strip end.
__device__ __forceinline__ void pool_flush(int b, int c4, float4 sum, float4 mx, int nodes) {
    float* ps = &g_psum[b * FG + c4];
    asm volatile("red.global.add.v4.f32 [%0], {%1,%2,%3,%4};"
                 :: "l"(ps), "f"(sum.x), "f"(sum.y), "f"(sum.z), "f"(sum.w) : "memory");
    int* pm = (int*)&g_pmax[b * FG + c4];
    atomicMax(pm + 0, __float_as_int(mx.x));
    atomicMax(pm + 1, __float_as_int(mx.y));
    atomicMax(pm + 2, __float_as_int(mx.z));
    atomicMax(pm + 3, __float_as_int(mx.w));
    if ((threadIdx.x & 31) == 0) atomicAdd(&g_cnt[b], (float)nodes);
}

__global__ void k_gather_pool(const int* __restrict__ batch, const float* __restrict__ bg, int N) {
    int warp = (blockIdx.x * blockDim.x + threadIdx.x) >> 5;
    int lane = threadIdx.x & 31;
    int n0 = warp * NODES_PER_WARP;
    if (n0 >= N) return;
    int n1 = n0 + NODES_PER_WARP; if (n1 > N) n1 = N;
    int c4 = lane * 4;
    float4 bv = *(const float4*)&bg[c4];

    float4 sum = make_float4(0.f, 0.f, 0.f, 0.f);
    float4 mx  = make_float4(0.f, 0.f, 0.f, 0.f);
    int cur_b = batch[n0];
    int nodes = 0;

    for (int n = n0; n < n1; n++) {
        int b = batch[n];
        if (b != cur_b) {
            pool_flush(cur_b, c4, sum, mx, nodes);
            sum = make_float4(0.f, 0.f, 0.f, 0.f);
            mx  = make_float4(0.f, 0.f, 0.f, 0.f);
            cur_b = b; nodes = 0;
        }
        // gather node n: self-loop + neighbors
        float4 acc = *(const float4*)&g_xws[(size_t)n * FG + c4];
        int start = g_rowptr[n];
        int cnt   = g_icnt[n];
        int e = 0;
        for (; e + 4 <= cnt; e += 4) {
            int s0 = g_csr[start + e    ];
            int s1 = g_csr[start + e + 1];
            int s2 = g_csr[start + e + 2];
            int s3 = g_csr[start + e + 3];
            float4 v0 = *(const float4*)&g_xws[(size_t)s0 * FG + c4];
            float4 v1 = *(const float4*)&g_xws[(size_t)s1 * FG + c4];
            float4 v2 = *(const float4*)&g_xws[(size_t)s2 * FG + c4];
            float4 v3 = *(const float4*)&g_xws[(size_t)s3 * FG + c4];
            acc.x += v0.x + v1.x + v2.x + v3.x;
            acc.y += v0.y + v1.y + v2.y + v3.y;
            acc.z += v0.z + v1.z + v2.z + v3.z;
            acc.w += v0.w + v1.w + v2.w + v3.w;
        }
        for (; e < cnt; e++) {
            int s = g_csr[start + e];
            float4 v = *(const float4*)&g_xws[(size_t)s * FG + c4];
            acc.x += v.x; acc.y += v.y; acc.z += v.z; acc.w += v.w;
        }
        float di = g_dinv[n];
        float v0 = fmaxf(fmaf(acc.x, di, bv.x), 0.f);
        float v1 = fmaxf(fmaf(acc.y, di, bv.y), 0.f);
        float v2 = fmaxf(fmaf(acc.z, di, bv.z), 0.f);
        float v3 = fmaxf(fmaf(acc.w, di, bv.w), 0.f);
        sum.x += v0; sum.y += v1; sum.z += v2; sum.w += v3;
        mx.x = fmaxf(mx.x, v0); mx.y = fmaxf(mx.y, v1);
        mx.z = fmaxf(mx.z, v2); mx.w = fmaxf(mx.w, v3);
        nodes++;
    }
    pool_flush(cur_b, c4, sum, mx, nodes);
}

// ---------------- head: encoder/decoder MLPs ----------------
__device__ __forceinline__ float eluf(float x)      { return x > 0.f ? x : expm1f(x); }
__device__ __forceinline__ float softplusf(float x) { return x > 20.f ? x : log1pf(expf(x)); }

__global__ void k_head(const float* __restrict__ eps,
                       const float* __restrict__ We1, const float* __restrict__ be1,
                       const float* __restrict__ We2, const float* __restrict__ be2,
                       const float* __restrict__ We3, const float* __restrict__ be3,
                       const float* __restrict__ Wd1, const float* __restrict__ bd1,
                       const float* __restrict__ Wd2, const float* __restrict__ bd2,
                       const float* __restrict__ Wd3, const float* __restrict__ bd3,
                       float* __restrict__ out, int G) {
    __shared__ float gx[2 * FG];
    __shared__ float t1[HID], t2[HID], ml[2 * ZD], zz[ZD], dd1[HID], dd2[HID];
    int g = blockIdx.x;
    int tid = threadIdx.x;

    float cnt = fmaxf(g_cnt[g], 1.0f);
    gx[tid]      = g_psum[g * FG + tid] / cnt;
    gx[FG + tid] = __int_as_float(g_pmax[g * FG + tid]);
    __syncthreads();

    if (tid < HID) {
        float s = be1[tid];
#pragma unroll 8
        for (int i = 0; i < 2 * FG; i++) s = fmaf(gx[i], We1[i * HID + tid], s);
        t1[tid] = eluf(s);
    }
    __syncthreads();
    if (tid < HID) {
        float s = be2[tid];
#pragma unroll 8
        for (int i = 0; i < HID; i++) s = fmaf(t1[i], We2[i * HID + tid], s);
        t2[tid] = tanhf(s);
    }
    __syncthreads();
    {
        float s = be3[tid];
#pragma unroll 8
        for (int i = 0; i < HID; i++) s = fmaf(t2[i], We3[i * 2 * ZD + tid], s);
        ml[tid] = s;
    }
    __syncthreads();
    if (tid < ZD) {
        float mu = ml[tid];
        float sd = 1e-6f + softplusf(ml[ZD + tid]);
        float z = fmaf(eps[g * ZD + tid], sd, mu);
        zz[tid] = z;
        out[g * ZD + tid] = mu;
        out[G * ZD + g * ZD + tid] = sd;
    }
    __syncthreads();
    if (tid < HID) {
        float s = bd1[tid];
#pragma unroll 8
        for (int i = 0; i < ZD; i++) s = fmaf(zz[i], Wd1[i * HID + tid], s);
        dd1[tid] = tanhf(s);
    }
    __syncthreads();
    if (tid < HID) {
        float s = bd2[tid];
#pragma unroll 8
        for (int i = 0; i < HID; i++) s = fmaf(dd1[i], Wd2[i * HID + tid], s);
        dd2[tid] = eluf(s);
    }
    __syncthreads();
    {
        float s = bd3[tid];
#pragma unroll 8
        for (int i = 0; i < HID; i++) s = fmaf(dd2[i], Wd3[i * FG + tid], s);
        float y = 1.0f / (1.0f + expf(-s));
        y = fminf(fmaxf(y, 1e-8f), 1.0f - 1e-8f);
        out[2 * G * ZD + g * FG + tid] = y;
    }
}

// ---------------- launch ----------------
extern "C" void kernel_launch(void* const* d_in, const int* in_sizes, int n_in,
                              void* d_out, int out_size) {
    const float* x     = (const float*)d_in[0];
    const int*   ei    = (const int*)  d_in[1];
    const int*   batch = (const int*)  d_in[2];
    const float* eps   = (const float*)d_in[3];
    const float* Wg    = (const float*)d_in[4];
    const float* bg    = (const float*)d_in[5];
    const float* We1 = (const float*)d_in[6],  *be1 = (const float*)d_in[7];
    const float* We2 = (const float*)d_in[8],  *be2 = (const float*)d_in[9];
    const float* We3 = (const float*)d_in[10], *be3 = (const float*)d_in[11];
    const float* Wd1 = (const float*)d_in[12], *bd1 = (const float*)d_in[13];
    const float* Wd2 = (const float*)d_in[14], *bd2 = (const float*)d_in[15];
    const float* Wd3 = (const float*)d_in[16], *bd3 = (const float*)d_in[17];
    float* out = (float*)d_out;

    int N = in_sizes[0] / FIN;       // 100000
    int E = in_sizes[1] / 2;         // 1600000
    int G = in_sizes[3] / ZD;        // 512
    const int* src = ei;
    const int* dst = ei + E;
    int nb = (N + SCAN_BLK - 1) / SCAN_BLK;

    int init_n = N > GMAX * FG ? N : GMAX * FG;
    k_init<<<(init_n + 255) / 256, 256>>>(N);
    k_deg<<<(E + 255) / 256, 256>>>(dst, E);
    k_dinv<<<(N + 255) / 256, 256>>>(N);
    k_scan1<<<nb, SCAN_BLK>>>(N);
    k_scan2<<<1, MAX_NB>>>(nb);
    k_scan3<<<(N + 255) / 256, 256>>>(N);
    k_fill<<<(E + 255) / 256, 256>>>(src, dst, E);
    k_gemm_tf32<<<(N + BM - 1) / BM, 256>>>(x, Wg, N);
    {
        int nwarps = (N + NODES_PER_WARP - 1) / NODES_PER_WARP;
        int nthreads = nwarps * 32;
        k_gather_pool<<<(nthreads + 255) / 256, 256>>>(batch, bg, N);
    }
    k_head<<<G, 128>>>(eps, We1, be1, We2, be2, We3, be3,
                       Wd1, bd1, Wd2, bd2, Wd3, bd3, out, G);
}